// round 1
// baseline (speedup 1.0000x reference)
#include <cuda_runtime.h>

// ---------------- problem constants ----------------
#define BATCH 4
#define SEQ   2048
#define DIM   640
#define HEADS 8
#define HDIM  80
#define RANK  4
#define BS    (BATCH*SEQ)          // 8192 rows
#define BSD   (BS*DIM)             // 5,242,880 elems

// ---------------- device scratch (no allocs allowed) ----------------
__device__ float g_wq[DIM*DIM];
__device__ float g_wk[DIM*DIM];
__device__ float g_wv[DIM*DIM];
__device__ float g_wo[DIM*DIM];
__device__ float g_q[BSD];
__device__ float g_k[BSD];
__device__ float g_v[BSD];
__device__ float g_attn[BSD];

// ---------------- f32x2 packed-math helpers ----------------
__device__ __forceinline__ unsigned long long f2_pack(float lo, float hi) {
    unsigned long long r;
    asm("mov.b64 %0, {%1, %2};" : "=l"(r) : "f"(lo), "f"(hi));
    return r;
}
__device__ __forceinline__ void f2_unpack(unsigned long long v, float& lo, float& hi) {
    asm("mov.b64 {%0, %1}, %2;" : "=f"(lo), "=f"(hi) : "l"(v));
}
__device__ __forceinline__ unsigned long long f2_fma(unsigned long long a,
                                                     unsigned long long b,
                                                     unsigned long long c) {
    unsigned long long d;
    asm("fma.rn.f32x2 %0, %1, %2, %3;" : "=l"(d) : "l"(a), "l"(b), "l"(c));
    return d;
}
__device__ __forceinline__ unsigned long long f2_mul(unsigned long long a,
                                                     unsigned long long b) {
    unsigned long long d;
    asm("mul.rn.f32x2 %0, %1, %2;" : "=l"(d) : "l"(a), "l"(b));
    return d;
}

// ---------------- fold LoRA into dense weights ----------------
// W_eff[o][i] = W[o][i] + sum_r up[o][r] * down[r][i]
__global__ void fold_weights(const float* __restrict__ wq, const float* __restrict__ wk,
                             const float* __restrict__ wv, const float* __restrict__ wo,
                             const float* __restrict__ qd, const float* __restrict__ qu,
                             const float* __restrict__ kd, const float* __restrict__ ku,
                             const float* __restrict__ vd, const float* __restrict__ vu,
                             const float* __restrict__ od, const float* __restrict__ ou) {
    const float *w, *dn, *up;
    float* out;
    switch (blockIdx.y) {
        case 0:  w = wq; dn = qd; up = qu; out = g_wq; break;
        case 1:  w = wk; dn = kd; up = ku; out = g_wk; break;
        case 2:  w = wv; dn = vd; up = vu; out = g_wv; break;
        default: w = wo; dn = od; up = ou; out = g_wo; break;
    }
    int idx = blockIdx.x * blockDim.x + threadIdx.x;
    if (idx >= DIM * DIM) return;
    int o = idx / DIM;
    int i = idx - o * DIM;
    float s = w[idx];
#pragma unroll
    for (int r = 0; r < RANK; r++)
        s += up[o * RANK + r] * dn[r * DIM + i];
    out[idx] = s;
}

// ---------------- SGEMM NT body: C[8192,640] = A[8192,640] * W[640,640]^T (+bias) ----------------
// BM=BN=128, BK=16, 256 threads, 8x8 per thread (as 8 x 4 f32x2 pairs).
__device__ __forceinline__ void gemm_body(const float* __restrict__ A,
                                          const float* __restrict__ W,
                                          const float* __restrict__ bias,
                                          float* __restrict__ C) {
    __shared__ float As[16 * 128];
    __shared__ float Bs[16 * 128];

    const int tid = threadIdx.x;
    const int tx = tid & 15;        // 0..15  -> N micro (8 cols)
    const int ty = tid >> 4;        // 0..15  -> M micro (8 rows)
    const int bm = blockIdx.y;      // 0..63
    const int bn = blockIdx.x;      // 0..4

    const float* Ab = A + (size_t)bm * 128 * DIM;
    const float* Wb = W + (size_t)bn * 128 * DIM;

    unsigned long long acc[8][4];
#pragma unroll
    for (int i = 0; i < 8; i++)
#pragma unroll
        for (int j = 0; j < 4; j++) acc[i][j] = 0ULL;

    const int lr = tid >> 2;              // 0..63
    const int lc = (tid & 3) * 4;         // 0,4,8,12

    for (int kt = 0; kt < DIM; kt += 16) {
        __syncthreads();
        float4 a0 = *(const float4*)(Ab + (size_t)lr * DIM + kt + lc);
        float4 a1 = *(const float4*)(Ab + (size_t)(lr + 64) * DIM + kt + lc);
        float4 b0 = *(const float4*)(Wb + (size_t)lr * DIM + kt + lc);
        float4 b1 = *(const float4*)(Wb + (size_t)(lr + 64) * DIM + kt + lc);
        As[(lc + 0) * 128 + lr] = a0.x;  As[(lc + 1) * 128 + lr] = a0.y;
        As[(lc + 2) * 128 + lr] = a0.z;  As[(lc + 3) * 128 + lr] = a0.w;
        As[(lc + 0) * 128 + lr + 64] = a1.x;  As[(lc + 1) * 128 + lr + 64] = a1.y;
        As[(lc + 2) * 128 + lr + 64] = a1.z;  As[(lc + 3) * 128 + lr + 64] = a1.w;
        Bs[(lc + 0) * 128 + lr] = b0.x;  Bs[(lc + 1) * 128 + lr] = b0.y;
        Bs[(lc + 2) * 128 + lr] = b0.z;  Bs[(lc + 3) * 128 + lr] = b0.w;
        Bs[(lc + 0) * 128 + lr + 64] = b1.x;  Bs[(lc + 1) * 128 + lr + 64] = b1.y;
        Bs[(lc + 2) * 128 + lr + 64] = b1.z;  Bs[(lc + 3) * 128 + lr + 64] = b1.w;
        __syncthreads();

#pragma unroll
        for (int k = 0; k < 16; k++) {
            float4 av0 = *(const float4*)&As[k * 128 + ty * 8];
            float4 av1 = *(const float4*)&As[k * 128 + ty * 8 + 4];
            ulonglong2 bv0 = *(const ulonglong2*)&Bs[k * 128 + tx * 8];
            ulonglong2 bv1 = *(const ulonglong2*)&Bs[k * 128 + tx * 8 + 4];
            unsigned long long bb[4] = {bv0.x, bv0.y, bv1.x, bv1.y};
            float am[8] = {av0.x, av0.y, av0.z, av0.w, av1.x, av1.y, av1.z, av1.w};
#pragma unroll
            for (int i = 0; i < 8; i++) {
                unsigned long long aa = f2_pack(am[i], am[i]);
#pragma unroll
                for (int j = 0; j < 4; j++) acc[i][j] = f2_fma(aa, bb[j], acc[i][j]);
            }
        }
    }

#pragma unroll
    for (int i = 0; i < 8; i++) {
        int m = bm * 128 + ty * 8 + i;
        float* Crow = C + (size_t)m * DIM + bn * 128 + tx * 8;
#pragma unroll
        for (int j = 0; j < 4; j++) {
            float lo, hi;
            f2_unpack(acc[i][j], lo, hi);
            if (bias) {
                int n = bn * 128 + tx * 8 + 2 * j;
                lo += bias[n];
                hi += bias[n + 1];
            }
            *(float2*)(Crow + 2 * j) = make_float2(lo, hi);
        }
    }
}

__global__ void __launch_bounds__(256, 2) qkv_gemm(const float* __restrict__ X) {
    const float* W;
    float* C;
    if (blockIdx.z == 0)      { W = g_wq; C = g_q; }
    else if (blockIdx.z == 1) { W = g_wk; C = g_k; }
    else                      { W = g_wv; C = g_v; }
    gemm_body(X, W, nullptr, C);
}

__global__ void __launch_bounds__(256, 2) out_gemm(const float* __restrict__ bias,
                                                   float* __restrict__ C) {
    gemm_body(g_attn, g_wo, bias, C);
}

// ---------------- flash attention, 64x64 tiles, hd=80, fp32 ----------------
// smem layout (floats):
//   sQ  [64][81]  at 0        (5184)
//   sKt [80][68]  at 5184     (5440)   K transposed: [k][key]
//   sV  [64][84]  at 10624    (5376)
//   sS  [64][65]  at 16000    (4160)
//   sM/sL/sC 64 each at 20160 / 20224 / 20288
#define FLASH_SMEM_FLOATS 20352
#define FLASH_SMEM_BYTES  (FLASH_SMEM_FLOATS * 4)

__global__ void __launch_bounds__(128) flash_attn() {
    extern __shared__ float sm[];
    float* sQ  = sm;
    float* sKt = sm + 5184;
    float* sV  = sm + 10624;
    float* sS  = sm + 16000;
    float* sM  = sm + 20160;
    float* sL  = sm + 20224;
    float* sC  = sm + 20288;

    const int tid = threadIdx.x;
    const int qt = blockIdx.x;   // 0..31
    const int h  = blockIdx.y;   // 0..7
    const int b  = blockIdx.z;   // 0..3

    const float scale = 0.11180339887498949f;   // 1/sqrt(80)

    const size_t baseQ = ((size_t)b * SEQ + qt * 64) * DIM + h * HDIM;

    // load Q tile: 64 rows x 80 cols = 1280 float4 loads / 128 threads
#pragma unroll
    for (int t = 0; t < 10; t++) {
        int idx = tid + t * 128;
        int r = idx / 20;
        int c = (idx % 20) * 4;
        float4 v = *(const float4*)(g_q + baseQ + (size_t)r * DIM + c);
        sQ[r * 81 + c + 0] = v.x;
        sQ[r * 81 + c + 1] = v.y;
        sQ[r * 81 + c + 2] = v.z;
        sQ[r * 81 + c + 3] = v.w;
    }
    if (tid < 64) { sM[tid] = -1e30f; sL[tid] = 0.f; }

    unsigned long long acc[4][5];
#pragma unroll
    for (int i = 0; i < 4; i++)
#pragma unroll
        for (int j = 0; j < 5; j++) acc[i][j] = 0ULL;

    const int r0 = (tid >> 3) * 4;       // 0,4,...,60
    const int cS = (tid & 7) * 8;        // 0..56
    const int cV = (tid & 7) * 10;       // 0..70

    for (int kt = 0; kt < SEQ / 64; kt++) {
        __syncthreads();   // protect sKt/sV (and initial sQ/sM) before overwrite/use
        const size_t baseK = ((size_t)b * SEQ + kt * 64) * DIM + h * HDIM;
#pragma unroll
        for (int t = 0; t < 10; t++) {
            int idx = tid + t * 128;
            int r = idx / 20;
            int c = (idx % 20) * 4;
            float4 kv = *(const float4*)(g_k + baseK + (size_t)r * DIM + c);
            sKt[(c + 0) * 68 + r] = kv.x;
            sKt[(c + 1) * 68 + r] = kv.y;
            sKt[(c + 2) * 68 + r] = kv.z;
            sKt[(c + 3) * 68 + r] = kv.w;
            float4 vv = *(const float4*)(g_v + baseK + (size_t)r * DIM + c);
            *(float4*)&sV[r * 84 + c] = vv;
        }
        __syncthreads();

        // ---- S = scale * Q K^T  (4 rows x 8 cols per thread, f32x2 pairs) ----
        unsigned long long s2[4][4];
#pragma unroll
        for (int i = 0; i < 4; i++)
#pragma unroll
            for (int j = 0; j < 4; j++) s2[i][j] = 0ULL;

#pragma unroll 4
        for (int k = 0; k < HDIM; k++) {
            ulonglong2 b01 = *(const ulonglong2*)&sKt[k * 68 + cS];
            ulonglong2 b23 = *(const ulonglong2*)&sKt[k * 68 + cS + 4];
#pragma unroll
            for (int i = 0; i < 4; i++) {
                float a = sQ[(r0 + i) * 81 + k];
                unsigned long long aa = f2_pack(a, a);
                s2[i][0] = f2_fma(aa, b01.x, s2[i][0]);
                s2[i][1] = f2_fma(aa, b01.y, s2[i][1]);
                s2[i][2] = f2_fma(aa, b23.x, s2[i][2]);
                s2[i][3] = f2_fma(aa, b23.y, s2[i][3]);
            }
        }
#pragma unroll
        for (int i = 0; i < 4; i++)
#pragma unroll
            for (int j = 0; j < 4; j++) {
                float lo, hi;
                f2_unpack(s2[i][j], lo, hi);
                sS[(r0 + i) * 65 + cS + 2 * j]     = lo * scale;
                sS[(r0 + i) * 65 + cS + 2 * j + 1] = hi * scale;
            }
        __syncthreads();

        // ---- online softmax, one row per thread (tid < 64) ----
        if (tid < 64) {
            float* row = sS + tid * 65;
            float mo = sM[tid];
            float mx = mo;
#pragma unroll 8
            for (int j = 0; j < 64; j++) mx = fmaxf(mx, row[j]);
            float corr = __expf(mo - mx);
            float sum = 0.f;
#pragma unroll 8
            for (int j = 0; j < 64; j++) {
                float p = __expf(row[j] - mx);
                row[j] = p;
                sum += p;
            }
            sL[tid] = sL[tid] * corr + sum;
            sM[tid] = mx;
            sC[tid] = corr;
        }
        __syncthreads();

        // ---- rescale accumulators, then O += P V  (4 rows x 10 cols) ----
#pragma unroll
        for (int i = 0; i < 4; i++) {
            float c = sC[r0 + i];
            unsigned long long cc = f2_pack(c, c);
#pragma unroll
            for (int j = 0; j < 5; j++) acc[i][j] = f2_mul(acc[i][j], cc);
        }
#pragma unroll 2
        for (int kk = 0; kk < 64; kk++) {
            unsigned long long vv[5];
#pragma unroll
            for (int j = 0; j < 5; j++)
                vv[j] = *(const unsigned long long*)&sV[kk * 84 + cV + 2 * j];
#pragma unroll
            for (int i = 0; i < 4; i++) {
                float p = sS[(r0 + i) * 65 + kk];
                unsigned long long pp = f2_pack(p, p);
#pragma unroll
                for (int j = 0; j < 5; j++) acc[i][j] = f2_fma(pp, vv[j], acc[i][j]);
            }
        }
    }

    // ---- epilogue: O /= l, write to g_attn in [B,S,D] layout ----
#pragma unroll
    for (int i = 0; i < 4; i++) {
        float inv = 1.f / sL[r0 + i];
        size_t o = ((size_t)b * SEQ + qt * 64 + r0 + i) * DIM + h * HDIM + cV;
#pragma unroll
        for (int j = 0; j < 5; j++) {
            float lo, hi;
            f2_unpack(acc[i][j], lo, hi);
            *(float2*)(g_attn + o + 2 * j) = make_float2(lo * inv, hi * inv);
        }
    }
}

// ---------------- launch ----------------
extern "C" void kernel_launch(void* const* d_in, const int* in_sizes, int n_in,
                              void* d_out, int out_size) {
    (void)in_sizes; (void)n_in; (void)out_size;
    const float* x  = (const float*)d_in[0];
    const float* wq = (const float*)d_in[1];
    const float* wk = (const float*)d_in[2];
    const float* wv = (const float*)d_in[3];
    const float* wo = (const float*)d_in[4];
    const float* bo = (const float*)d_in[5];
    const float* qd = (const float*)d_in[6];
    const float* qu = (const float*)d_in[7];
    const float* kd = (const float*)d_in[8];
    const float* ku = (const float*)d_in[9];
    const float* vd = (const float*)d_in[10];
    const float* vu = (const float*)d_in[11];
    const float* od = (const float*)d_in[12];
    const float* ou = (const float*)d_in[13];
    float* out = (float*)d_out;

    // 1) fold LoRA into dense weights
    fold_weights<<<dim3((DIM * DIM + 255) / 256, 4), 256>>>(
        wq, wk, wv, wo, qd, qu, kd, ku, vd, vu, od, ou);

    // 2) Q/K/V projections, one fat launch (z selects head matrix)
    qkv_gemm<<<dim3(DIM / 128, BS / 128, 3), 256>>>(x);

    // 3) flash attention
    cudaFuncSetAttribute(flash_attn, cudaFuncAttributeMaxDynamicSharedMemorySize,
                         FLASH_SMEM_BYTES);
    flash_attn<<<dim3(SEQ / 64, HEADS, BATCH), 128, FLASH_SMEM_BYTES>>>();

    // 4) output projection + bias (LoRA already folded into g_wo)
    out_gemm<<<dim3(DIM / 128, BS / 128), 256>>>(bo, out);
}

// round 2
// speedup vs baseline: 1.0719x; 1.0719x over previous
#include <cuda_runtime.h>

// ---------------- problem constants ----------------
#define BATCH 4
#define SEQ   2048
#define DIM   640
#define HEADS 8
#define HDIM  80
#define RANK  4
#define BS    (BATCH*SEQ)          // 8192 rows
#define BSD   (BS*DIM)             // 5,242,880 elems

// ---------------- device scratch (no allocs allowed) ----------------
__device__ float g_wq[DIM*DIM];
__device__ float g_wk[DIM*DIM];
__device__ float g_wv[DIM*DIM];
__device__ float g_wo[DIM*DIM];
__device__ float g_q[BSD];
__device__ float g_k[BSD];
__device__ float g_v[BSD];
__device__ float g_attn[BSD];

// ---------------- f32x2 packed-math helpers ----------------
__device__ __forceinline__ unsigned long long f2_pack(float lo, float hi) {
    unsigned long long r;
    asm("mov.b64 %0, {%1, %2};" : "=l"(r) : "f"(lo), "f"(hi));
    return r;
}
__device__ __forceinline__ void f2_unpack(unsigned long long v, float& lo, float& hi) {
    asm("mov.b64 {%0, %1}, %2;" : "=f"(lo), "=f"(hi) : "l"(v));
}
__device__ __forceinline__ unsigned long long f2_fma(unsigned long long a,
                                                     unsigned long long b,
                                                     unsigned long long c) {
    unsigned long long d;
    asm("fma.rn.f32x2 %0, %1, %2, %3;" : "=l"(d) : "l"(a), "l"(b), "l"(c));
    return d;
}
__device__ __forceinline__ unsigned long long f2_mul(unsigned long long a,
                                                     unsigned long long b) {
    unsigned long long d;
    asm("mul.rn.f32x2 %0, %1, %2;" : "=l"(d) : "l"(a), "l"(b));
    return d;
}

// ---------------- fold LoRA into dense weights ----------------
__global__ void fold_weights(const float* __restrict__ wq, const float* __restrict__ wk,
                             const float* __restrict__ wv, const float* __restrict__ wo,
                             const float* __restrict__ qd, const float* __restrict__ qu,
                             const float* __restrict__ kd, const float* __restrict__ ku,
                             const float* __restrict__ vd, const float* __restrict__ vu,
                             const float* __restrict__ od, const float* __restrict__ ou) {
    const float *w, *dn, *up;
    float* out;
    switch (blockIdx.y) {
        case 0:  w = wq; dn = qd; up = qu; out = g_wq; break;
        case 1:  w = wk; dn = kd; up = ku; out = g_wk; break;
        case 2:  w = wv; dn = vd; up = vu; out = g_wv; break;
        default: w = wo; dn = od; up = ou; out = g_wo; break;
    }
    int idx = blockIdx.x * blockDim.x + threadIdx.x;
    if (idx >= DIM * DIM) return;
    int o = idx / DIM;
    int i = idx - o * DIM;
    float s = w[idx];
#pragma unroll
    for (int r = 0; r < RANK; r++)
        s += up[o * RANK + r] * dn[r * DIM + i];
    out[idx] = s;
}

// ---------------- double-buffered SGEMM NT: C = A[8192,640] * W[640,640]^T (+bias) ----
// BM=BN=128, BK=16, 256 threads, 8x8 per thread as f32x2 pairs, 2-stage smem.
__device__ __forceinline__ void sts_tile(float* As, float* Bs, int lr, int lc,
                                         float4 a0, float4 a1, float4 b0, float4 b1) {
    As[(lc + 0) * 128 + lr] = a0.x;  As[(lc + 1) * 128 + lr] = a0.y;
    As[(lc + 2) * 128 + lr] = a0.z;  As[(lc + 3) * 128 + lr] = a0.w;
    As[(lc + 0) * 128 + lr + 64] = a1.x;  As[(lc + 1) * 128 + lr + 64] = a1.y;
    As[(lc + 2) * 128 + lr + 64] = a1.z;  As[(lc + 3) * 128 + lr + 64] = a1.w;
    Bs[(lc + 0) * 128 + lr] = b0.x;  Bs[(lc + 1) * 128 + lr] = b0.y;
    Bs[(lc + 2) * 128 + lr] = b0.z;  Bs[(lc + 3) * 128 + lr] = b0.w;
    Bs[(lc + 0) * 128 + lr + 64] = b1.x;  Bs[(lc + 1) * 128 + lr + 64] = b1.y;
    Bs[(lc + 2) * 128 + lr + 64] = b1.z;  Bs[(lc + 3) * 128 + lr + 64] = b1.w;
}

__device__ __forceinline__ void gemm_body(const float* __restrict__ A,
                                          const float* __restrict__ W,
                                          const float* __restrict__ bias,
                                          float* __restrict__ C) {
    __shared__ float As[2][16 * 128];
    __shared__ float Bs[2][16 * 128];

    const int tid = threadIdx.x;
    const int tx = tid & 15;
    const int ty = tid >> 4;
    const int bm = blockIdx.y;
    const int bn = blockIdx.x;

    const float* Ab = A + (size_t)bm * 128 * DIM;
    const float* Wb = W + (size_t)bn * 128 * DIM;

    unsigned long long acc[8][4];
#pragma unroll
    for (int i = 0; i < 8; i++)
#pragma unroll
        for (int j = 0; j < 4; j++) acc[i][j] = 0ULL;

    const int lr = tid >> 2;
    const int lc = (tid & 3) * 4;

    // prefetch tile 0
    {
        float4 a0 = *(const float4*)(Ab + (size_t)lr * DIM + lc);
        float4 a1 = *(const float4*)(Ab + (size_t)(lr + 64) * DIM + lc);
        float4 b0 = *(const float4*)(Wb + (size_t)lr * DIM + lc);
        float4 b1 = *(const float4*)(Wb + (size_t)(lr + 64) * DIM + lc);
        sts_tile(As[0], Bs[0], lr, lc, a0, a1, b0, b1);
    }
    __syncthreads();

#pragma unroll 1
    for (int kt = 0; kt < DIM / 16; kt++) {
        const int cur = kt & 1;
        float4 na0, na1, nb0, nb1;
        if (kt < DIM / 16 - 1) {
            int off = (kt + 1) * 16 + lc;
            na0 = *(const float4*)(Ab + (size_t)lr * DIM + off);
            na1 = *(const float4*)(Ab + (size_t)(lr + 64) * DIM + off);
            nb0 = *(const float4*)(Wb + (size_t)lr * DIM + off);
            nb1 = *(const float4*)(Wb + (size_t)(lr + 64) * DIM + off);
        }
        const float* Ac = As[cur];
        const float* Bc = Bs[cur];
#pragma unroll
        for (int k = 0; k < 16; k++) {
            float4 av0 = *(const float4*)&Ac[k * 128 + ty * 8];
            float4 av1 = *(const float4*)&Ac[k * 128 + ty * 8 + 4];
            ulonglong2 bv0 = *(const ulonglong2*)&Bc[k * 128 + tx * 8];
            ulonglong2 bv1 = *(const ulonglong2*)&Bc[k * 128 + tx * 8 + 4];
            unsigned long long bb[4] = {bv0.x, bv0.y, bv1.x, bv1.y};
            float am[8] = {av0.x, av0.y, av0.z, av0.w, av1.x, av1.y, av1.z, av1.w};
#pragma unroll
            for (int i = 0; i < 8; i++) {
                unsigned long long aa = f2_pack(am[i], am[i]);
#pragma unroll
                for (int j = 0; j < 4; j++) acc[i][j] = f2_fma(aa, bb[j], acc[i][j]);
            }
        }
        if (kt < DIM / 16 - 1) {
            sts_tile(As[cur ^ 1], Bs[cur ^ 1], lr, lc, na0, na1, nb0, nb1);
            __syncthreads();
        }
    }

#pragma unroll
    for (int i = 0; i < 8; i++) {
        int m = bm * 128 + ty * 8 + i;
        float* Crow = C + (size_t)m * DIM + bn * 128 + tx * 8;
#pragma unroll
        for (int j = 0; j < 4; j++) {
            float lo, hi;
            f2_unpack(acc[i][j], lo, hi);
            if (bias) {
                int n = bn * 128 + tx * 8 + 2 * j;
                lo += bias[n];
                hi += bias[n + 1];
            }
            *(float2*)(Crow + 2 * j) = make_float2(lo, hi);
        }
    }
}

__global__ void __launch_bounds__(256, 2) qkv_gemm(const float* __restrict__ X) {
    const float* W;
    float* C;
    if (blockIdx.z == 0)      { W = g_wq; C = g_q; }
    else if (blockIdx.z == 1) { W = g_wk; C = g_k; }
    else                      { W = g_wv; C = g_v; }
    gemm_body(X, W, nullptr, C);
}

__global__ void __launch_bounds__(256, 2) out_gemm(const float* __restrict__ bias,
                                                   float* __restrict__ C) {
    gemm_body(g_attn, g_wo, bias, C);
}

// ---------------- flash attention v2: S^T formulation, no per-tile transpose ------
// 64 queries x 64 keys per tile, 128 threads, hd=80.
// smem (floats):
//   sQt [80][68]  at 0      (5440)  Q transposed: [k][query] (transposed ONCE)
//   sK  [64][88]  at 5440   (5632)  K row-major [key][k]   (pad 88: a-frag wf=1)
//   sV  [64][80]  at 11072  (5120)  V row-major [key][d]
//   sSt [64][68]  at 16192  (4352)  S^T / P^T: [key][query]
//   sM/sL/sC 64 each at 20544/20608/20672
#define QPAD 68
#define KPAD 88
#define VPAD 80
#define FLASH_SMEM_FLOATS 20736
#define FLASH_SMEM_BYTES  (FLASH_SMEM_FLOATS * 4)

__global__ void __launch_bounds__(128) flash_attn() {
    extern __shared__ float sm[];
    float* sQt = sm;
    float* sK  = sm + 5440;
    float* sV  = sm + 11072;
    float* sSt = sm + 16192;
    float* sM  = sm + 20544;
    float* sL  = sm + 20608;
    float* sC  = sm + 20672;

    const int tid = threadIdx.x;
    const int qt = blockIdx.x;   // 0..31
    const int h  = blockIdx.y;   // 0..7
    const int b  = blockIdx.z;   // 0..3

    const float scale = 0.11180339887498949f;   // 1/sqrt(80)
    const unsigned long long scale2 = f2_pack(scale, scale);

    const size_t baseQ = ((size_t)b * SEQ + qt * 64) * DIM + h * HDIM;

    // ---- load Q transposed (once per block): sQt[k][q] ----
    // writes conflict-free (consecutive threads -> consecutive q); gmem reads
    // scattered but L2-resident (amortized over 32 key tiles).
#pragma unroll
    for (int t = 0; t < 40; t++) {
        int idx = tid + t * 128;          // 5120 = 80*64
        int k = idx >> 6;
        int q = idx & 63;
        sQt[k * QPAD + q] = g_q[baseQ + (size_t)q * DIM + k];
    }
    if (tid < 64) { sM[tid] = -1e30f; sL[tid] = 0.f; }

    const int j0 = (tid >> 3) * 4;        // 4 keys (S^T rows) / 4 queries in PV
    const int i0 = (tid & 7) * 8;         // 8 queries (S^T cols)
    const int cV = (tid & 7) * 10;        // 10 head-dims in PV

    unsigned long long acc[4][5];
#pragma unroll
    for (int i = 0; i < 4; i++)
#pragma unroll
        for (int j = 0; j < 5; j++) acc[i][j] = 0ULL;

    for (int kt = 0; kt < SEQ / 64; kt++) {
        __syncthreads();   // previous PV done reading sSt/sV; sK free
        const size_t baseK = ((size_t)b * SEQ + kt * 64) * DIM + h * HDIM;
#pragma unroll
        for (int t = 0; t < 10; t++) {
            int idx = tid + t * 128;
            int r = idx / 20;
            int c = (idx % 20) * 4;
            float4 kv = *(const float4*)(g_k + baseK + (size_t)r * DIM + c);
            float4 vv = *(const float4*)(g_v + baseK + (size_t)r * DIM + c);
            *(float4*)&sK[r * KPAD + c] = kv;
            *(float4*)&sV[r * VPAD + c] = vv;
        }
        __syncthreads();

        // ---- S^T[j][i] = sum_k K[j][k] * Qt[k][i],  4x8 per thread ----
        unsigned long long s2[4][4];
#pragma unroll
        for (int i = 0; i < 4; i++)
#pragma unroll
            for (int j = 0; j < 4; j++) s2[i][j] = 0ULL;

#pragma unroll
        for (int kb = 0; kb < HDIM; kb += 4) {
            float4 aK[4];
#pragma unroll
            for (int u = 0; u < 4; u++)
                aK[u] = *(const float4*)&sK[(j0 + u) * KPAD + kb];
#pragma unroll
            for (int kk = 0; kk < 4; kk++) {
                const float* qrow = &sQt[(kb + kk) * QPAD + i0];
                ulonglong2 b01 = *(const ulonglong2*)qrow;
                ulonglong2 b23 = *(const ulonglong2*)(qrow + 4);
                unsigned long long bb[4] = {b01.x, b01.y, b23.x, b23.y};
#pragma unroll
                for (int u = 0; u < 4; u++) {
                    float a = ((const float*)&aK[u])[kk];
                    unsigned long long aa = f2_pack(a, a);
#pragma unroll
                    for (int m = 0; m < 4; m++)
                        s2[u][m] = f2_fma(aa, bb[m], s2[u][m]);
                }
            }
        }
#pragma unroll
        for (int u = 0; u < 4; u++)
#pragma unroll
            for (int m = 0; m < 4; m++)
                *(unsigned long long*)&sSt[(j0 + u) * QPAD + i0 + 2 * m] =
                    f2_mul(s2[u][m], scale2);
        __syncthreads();

        // ---- online softmax: one query column per thread (conflict-free) ----
        if (tid < 64) {
            const int q = tid;
            float mo = sM[q];
            float mx = mo;
#pragma unroll 8
            for (int kk = 0; kk < 64; kk++) mx = fmaxf(mx, sSt[kk * QPAD + q]);
            float corr = __expf(mo - mx);
            float sum = 0.f;
#pragma unroll 8
            for (int kk = 0; kk < 64; kk++) {
                float p = __expf(sSt[kk * QPAD + q] - mx);
                sSt[kk * QPAD + q] = p;
                sum += p;
            }
            sL[q] = sL[q] * corr + sum;
            sM[q] = mx;
            sC[q] = corr;
        }
        __syncthreads();

        // ---- rescale accumulators, then O += P V  (4 queries x 10 dims) ----
#pragma unroll
        for (int i = 0; i < 4; i++) {
            float c = sC[j0 + i];
            unsigned long long cc = f2_pack(c, c);
#pragma unroll
            for (int j = 0; j < 5; j++) acc[i][j] = f2_mul(acc[i][j], cc);
        }
#pragma unroll 2
        for (int kk = 0; kk < 64; kk++) {
            float4 pv = *(const float4*)&sSt[kk * QPAD + j0];   // P for 4 queries
            unsigned long long vv[5];
#pragma unroll
            for (int j = 0; j < 5; j++)
                vv[j] = *(const unsigned long long*)&sV[kk * VPAD + cV + 2 * j];
            float pm[4] = {pv.x, pv.y, pv.z, pv.w};
#pragma unroll
            for (int i = 0; i < 4; i++) {
                unsigned long long pp = f2_pack(pm[i], pm[i]);
#pragma unroll
                for (int j = 0; j < 5; j++) acc[i][j] = f2_fma(pp, vv[j], acc[i][j]);
            }
        }
    }

    // ---- epilogue: O /= l, write to g_attn [B,S,D] ----
#pragma unroll
    for (int i = 0; i < 4; i++) {
        float inv = 1.f / sL[j0 + i];
        size_t o = ((size_t)b * SEQ + qt * 64 + j0 + i) * DIM + h * HDIM + cV;
#pragma unroll
        for (int j = 0; j < 5; j++) {
            float lo, hi;
            f2_unpack(acc[i][j], lo, hi);
            *(float2*)(g_attn + o + 2 * j) = make_float2(lo * inv, hi * inv);
        }
    }
}

// ---------------- launch ----------------
extern "C" void kernel_launch(void* const* d_in, const int* in_sizes, int n_in,
                              void* d_out, int out_size) {
    (void)in_sizes; (void)n_in; (void)out_size;
    const float* x  = (const float*)d_in[0];
    const float* wq = (const float*)d_in[1];
    const float* wk = (const float*)d_in[2];
    const float* wv = (const float*)d_in[3];
    const float* wo = (const float*)d_in[4];
    const float* bo = (const float*)d_in[5];
    const float* qd = (const float*)d_in[6];
    const float* qu = (const float*)d_in[7];
    const float* kd = (const float*)d_in[8];
    const float* ku = (const float*)d_in[9];
    const float* vd = (const float*)d_in[10];
    const float* vu = (const float*)d_in[11];
    const float* od = (const float*)d_in[12];
    const float* ou = (const float*)d_in[13];
    float* out = (float*)d_out;

    fold_weights<<<dim3((DIM * DIM + 255) / 256, 4), 256>>>(
        wq, wk, wv, wo, qd, qu, kd, ku, vd, vu, od, ou);

    qkv_gemm<<<dim3(DIM / 128, BS / 128, 3), 256>>>(x);

    cudaFuncSetAttribute(flash_attn, cudaFuncAttributeMaxDynamicSharedMemorySize,
                         FLASH_SMEM_BYTES);
    flash_attn<<<dim3(SEQ / 64, HEADS, BATCH), 128, FLASH_SMEM_BYTES>>>();

    out_gemm<<<dim3(DIM / 128, BS / 128), 256>>>(bo, out);
}

// round 5
// speedup vs baseline: 1.2226x; 1.1405x over previous
#include <cuda_runtime.h>
#include <mma.h>
#include <cstdint>

using namespace nvcuda;

// ---------------- problem constants ----------------
#define BATCH 4
#define SEQ   2048
#define DIM   640
#define HEADS 8
#define HDIM  80
#define RANK  4
#define BS    (BATCH*SEQ)          // 8192 rows
#define BSD   (BS*DIM)             // 5,242,880 elems

// ---------------- device scratch (no allocs allowed) ----------------
__device__ float g_wq[DIM*DIM];
__device__ float g_wk[DIM*DIM];
__device__ float g_wv[DIM*DIM];
__device__ float g_wo[DIM*DIM];
__device__ float g_q[BSD];
__device__ float g_k[BSD];
__device__ float g_v[BSD];
__device__ float g_attn[BSD];

// ---------------- f32x2 packed-math helpers (flash) ----------------
__device__ __forceinline__ unsigned long long f2_pack(float lo, float hi) {
    unsigned long long r;
    asm("mov.b64 %0, {%1, %2};" : "=l"(r) : "f"(lo), "f"(hi));
    return r;
}
__device__ __forceinline__ void f2_unpack(unsigned long long v, float& lo, float& hi) {
    asm("mov.b64 {%0, %1}, %2;" : "=f"(lo), "=f"(hi) : "l"(v));
}
__device__ __forceinline__ unsigned long long f2_fma(unsigned long long a,
                                                     unsigned long long b,
                                                     unsigned long long c) {
    unsigned long long d;
    asm("fma.rn.f32x2 %0, %1, %2, %3;" : "=l"(d) : "l"(a), "l"(b), "l"(c));
    return d;
}
__device__ __forceinline__ unsigned long long f2_mul(unsigned long long a,
                                                     unsigned long long b) {
    unsigned long long d;
    asm("mul.rn.f32x2 %0, %1, %2;" : "=l"(d) : "l"(a), "l"(b));
    return d;
}

// ---------------- cp.async helpers (baseline PTX, no arch-a needed) ----------------
__device__ __forceinline__ uint32_t smem_u32(const void* p) {
    uint32_t a;
    asm("{ .reg .u64 t; cvta.to.shared.u64 t, %1; cvt.u32.u64 %0, t; }"
        : "=r"(a) : "l"(p));
    return a;
}
__device__ __forceinline__ void cp16(uint32_t s, const void* g) {
    asm volatile("cp.async.ca.shared.global [%0], [%1], 16;" :: "r"(s), "l"(g));
}
#define CP_COMMIT() asm volatile("cp.async.commit_group;" ::: "memory")
#define CP_WAIT(n)  asm volatile("cp.async.wait_group %0;" :: "n"(n) : "memory")

// ---------------- fold LoRA into dense weights ----------------
__global__ void fold_weights(const float* __restrict__ wq, const float* __restrict__ wk,
                             const float* __restrict__ wv, const float* __restrict__ wo,
                             const float* __restrict__ qd, const float* __restrict__ qu,
                             const float* __restrict__ kd, const float* __restrict__ ku,
                             const float* __restrict__ vd, const float* __restrict__ vu,
                             const float* __restrict__ od, const float* __restrict__ ou) {
    const float *w, *dn, *up;
    float* out;
    switch (blockIdx.y) {
        case 0:  w = wq; dn = qd; up = qu; out = g_wq; break;
        case 1:  w = wk; dn = kd; up = ku; out = g_wk; break;
        case 2:  w = wv; dn = vd; up = vu; out = g_wv; break;
        default: w = wo; dn = od; up = ou; out = g_wo; break;
    }
    int idx = blockIdx.x * blockDim.x + threadIdx.x;
    if (idx >= DIM * DIM) return;
    int o = idx / DIM;
    int i = idx - o * DIM;
    float s = w[idx];
#pragma unroll
    for (int r = 0; r < RANK; r++)
        s += up[o * RANK + r] * dn[r * DIM + i];
    out[idx] = s;
}

// ---------------- WMMA tf32 GEMM: C[8192,640] = A[8192,640] * W[640,640]^T (+bias) --
// CTA 128x128, BK=32, 256 threads = 8 warps in 2(M) x 4(N); warp tile 64x32.
// cp.async double-buffered smem, stride 40 floats (160B rows).
#define BK 32
#define LDS_STRIDE 40
#define TILE_FLOATS (128 * LDS_STRIDE)             // 5120
#define GEMM_SMEM_FLOATS (4 * TILE_FLOATS)         // 20480 (2 stages x {A,B})
#define GEMM_SMEM_BYTES  (GEMM_SMEM_FLOATS * 4)    // 81920
#define EPI_STRIDE 36

__device__ __forceinline__ void gemm_wmma_body(const float* __restrict__ A,
                                               const float* __restrict__ W,
                                               const float* __restrict__ bias,
                                               float* __restrict__ C) {
    extern __shared__ float sm[];
    float* sA[2] = { sm,            sm + 2 * TILE_FLOATS };
    float* sB[2] = { sm + TILE_FLOATS, sm + 3 * TILE_FLOATS };

    const int tid  = threadIdx.x;
    const int wid  = tid >> 5;
    const int lane = tid & 31;
    const int warp_m = wid >> 2;       // 0..1
    const int warp_n = wid & 3;        // 0..3
    const int bm = blockIdx.y;
    const int bn = blockIdx.x;

    const float* Ab = A + (size_t)bm * 128 * DIM;
    const float* Wb = W + (size_t)bn * 128 * DIM;

    // loader mapping: 1024 16B-slots per tile / 256 threads = 4 slots each
    const int r0 = tid >> 3;            // 0..31 (row group base)
    const int c4 = (tid & 7) * 4;       // k column (floats)

    wmma::fragment<wmma::accumulator, 16, 16, 8, float> acc[4][2];
#pragma unroll
    for (int mi = 0; mi < 4; mi++)
#pragma unroll
        for (int ni = 0; ni < 2; ni++) wmma::fill_fragment(acc[mi][ni], 0.0f);

    auto issue_stage = [&](int kt, int st) {
#pragma unroll
        for (int i = 0; i < 4; i++) {
            int row = r0 + i * 32;
            cp16(smem_u32(&sA[st][row * LDS_STRIDE + c4]),
                 Ab + (size_t)row * DIM + kt * BK + c4);
            cp16(smem_u32(&sB[st][row * LDS_STRIDE + c4]),
                 Wb + (size_t)row * DIM + kt * BK + c4);
        }
        CP_COMMIT();
    };

    issue_stage(0, 0);

    const int NKT = DIM / BK;   // 20
#pragma unroll 1
    for (int kt = 0; kt < NKT; kt++) {
        const int st = kt & 1;
        if (kt + 1 < NKT) {
            issue_stage(kt + 1, st ^ 1);
            CP_WAIT(1);
        } else {
            CP_WAIT(0);
        }
        __syncthreads();

        const float* Ac = sA[st];
        const float* Bc = sB[st];
#pragma unroll
        for (int ks = 0; ks < 4; ks++) {
            wmma::fragment<wmma::matrix_a, 16, 16, 8, wmma::precision::tf32,
                           wmma::row_major> af[4];
            wmma::fragment<wmma::matrix_b, 16, 16, 8, wmma::precision::tf32,
                           wmma::col_major> bf[2];
#pragma unroll
            for (int mi = 0; mi < 4; mi++) {
                wmma::load_matrix_sync(
                    af[mi], Ac + (warp_m * 64 + mi * 16) * LDS_STRIDE + ks * 8,
                    LDS_STRIDE);
#pragma unroll
                for (int e = 0; e < af[mi].num_elements; e++)
                    af[mi].x[e] = wmma::__float_to_tf32(af[mi].x[e]);
            }
#pragma unroll
            for (int ni = 0; ni < 2; ni++) {
                wmma::load_matrix_sync(
                    bf[ni], Bc + (warp_n * 32 + ni * 16) * LDS_STRIDE + ks * 8,
                    LDS_STRIDE);
#pragma unroll
                for (int e = 0; e < bf[ni].num_elements; e++)
                    bf[ni].x[e] = wmma::__float_to_tf32(bf[ni].x[e]);
            }
#pragma unroll
            for (int mi = 0; mi < 4; mi++)
#pragma unroll
                for (int ni = 0; ni < 2; ni++)
                    wmma::mma_sync(acc[mi][ni], af[mi], bf[ni], acc[mi][ni]);
        }
        __syncthreads();
    }

    // ---- epilogue: stage through smem, coalesced biased stores ----
    float* stage = sm + wid * (64 * EPI_STRIDE);   // 2304 floats/warp, 18432 total
#pragma unroll
    for (int mi = 0; mi < 4; mi++)
#pragma unroll
        for (int ni = 0; ni < 2; ni++)
            wmma::store_matrix_sync(stage + (mi * 16) * EPI_STRIDE + ni * 16,
                                    acc[mi][ni], EPI_STRIDE, wmma::mem_row_major);
    __syncwarp();

    const int grow = bm * 128 + warp_m * 64;
    const int gcol = bn * 128 + warp_n * 32;
#pragma unroll
    for (int i = 0; i < 16; i++) {
        int s = lane + i * 32;          // 512 float4-slots (64 rows x 8)
        int row = s >> 3;
        int c = (s & 7) * 4;
        float4 v = *(const float4*)&stage[row * EPI_STRIDE + c];
        if (bias) {
            int n = gcol + c;
            v.x += bias[n]; v.y += bias[n + 1];
            v.z += bias[n + 2]; v.w += bias[n + 3];
        }
        *(float4*)(C + (size_t)(grow + row) * DIM + gcol + c) = v;
    }
}

__global__ void __launch_bounds__(256) qkv_gemm_w(const float* __restrict__ X) {
    const float* W;
    float* C;
    if (blockIdx.z == 0)      { W = g_wq; C = g_q; }
    else if (blockIdx.z == 1) { W = g_wk; C = g_k; }
    else                      { W = g_wv; C = g_v; }
    gemm_wmma_body(X, W, nullptr, C);
}
__global__ void __launch_bounds__(256) out_gemm_w(const float* __restrict__ bias,
                                                  float* __restrict__ C) {
    gemm_wmma_body(g_attn, g_wo, bias, C);
}

// ---------------- flash attention (unchanged from R2, FFMA2 fp32) ----------------
#define QPAD 68
#define KPAD 88
#define VPAD 80
#define FLASH_SMEM_FLOATS 20736
#define FLASH_SMEM_BYTES  (FLASH_SMEM_FLOATS * 4)

__global__ void __launch_bounds__(128) flash_attn() {
    extern __shared__ float sm[];
    float* sQt = sm;
    float* sK  = sm + 5440;
    float* sV  = sm + 11072;
    float* sSt = sm + 16192;
    float* sM  = sm + 20544;
    float* sL  = sm + 20608;
    float* sC  = sm + 20672;

    const int tid = threadIdx.x;
    const int qt = blockIdx.x;
    const int h  = blockIdx.y;
    const int b  = blockIdx.z;

    const float scale = 0.11180339887498949f;   // 1/sqrt(80)
    const unsigned long long scale2 = f2_pack(scale, scale);

    const size_t baseQ = ((size_t)b * SEQ + qt * 64) * DIM + h * HDIM;

#pragma unroll
    for (int t = 0; t < 40; t++) {
        int idx = tid + t * 128;
        int k = idx >> 6;
        int q = idx & 63;
        sQt[k * QPAD + q] = g_q[baseQ + (size_t)q * DIM + k];
    }
    if (tid < 64) { sM[tid] = -1e30f; sL[tid] = 0.f; }

    const int j0 = (tid >> 3) * 4;
    const int i0 = (tid & 7) * 8;
    const int cV = (tid & 7) * 10;

    unsigned long long acc[4][5];
#pragma unroll
    for (int i = 0; i < 4; i++)
#pragma unroll
        for (int j = 0; j < 5; j++) acc[i][j] = 0ULL;

    for (int kt = 0; kt < SEQ / 64; kt++) {
        __syncthreads();
        const size_t baseK = ((size_t)b * SEQ + kt * 64) * DIM + h * HDIM;
#pragma unroll
        for (int t = 0; t < 10; t++) {
            int idx = tid + t * 128;
            int r = idx / 20;
            int c = (idx % 20) * 4;
            float4 kv = *(const float4*)(g_k + baseK + (size_t)r * DIM + c);
            float4 vv = *(const float4*)(g_v + baseK + (size_t)r * DIM + c);
            *(float4*)&sK[r * KPAD + c] = kv;
            *(float4*)&sV[r * VPAD + c] = vv;
        }
        __syncthreads();

        unsigned long long s2[4][4];
#pragma unroll
        for (int i = 0; i < 4; i++)
#pragma unroll
            for (int j = 0; j < 4; j++) s2[i][j] = 0ULL;

#pragma unroll
        for (int kb = 0; kb < HDIM; kb += 4) {
            float4 aK[4];
#pragma unroll
            for (int u = 0; u < 4; u++)
                aK[u] = *(const float4*)&sK[(j0 + u) * KPAD + kb];
#pragma unroll
            for (int kk = 0; kk < 4; kk++) {
                const float* qrow = &sQt[(kb + kk) * QPAD + i0];
                ulonglong2 b01 = *(const ulonglong2*)qrow;
                ulonglong2 b23 = *(const ulonglong2*)(qrow + 4);
                unsigned long long bb[4] = {b01.x, b01.y, b23.x, b23.y};
#pragma unroll
                for (int u = 0; u < 4; u++) {
                    float a = ((const float*)&aK[u])[kk];
                    unsigned long long aa = f2_pack(a, a);
#pragma unroll
                    for (int m = 0; m < 4; m++)
                        s2[u][m] = f2_fma(aa, bb[m], s2[u][m]);
                }
            }
        }
#pragma unroll
        for (int u = 0; u < 4; u++)
#pragma unroll
            for (int m = 0; m < 4; m++)
                *(unsigned long long*)&sSt[(j0 + u) * QPAD + i0 + 2 * m] =
                    f2_mul(s2[u][m], scale2);
        __syncthreads();

        if (tid < 64) {
            const int q = tid;
            float mo = sM[q];
            float mx = mo;
#pragma unroll 8
            for (int kk = 0; kk < 64; kk++) mx = fmaxf(mx, sSt[kk * QPAD + q]);
            float corr = __expf(mo - mx);
            float sum = 0.f;
#pragma unroll 8
            for (int kk = 0; kk < 64; kk++) {
                float p = __expf(sSt[kk * QPAD + q] - mx);
                sSt[kk * QPAD + q] = p;
                sum += p;
            }
            sL[q] = sL[q] * corr + sum;
            sM[q] = mx;
            sC[q] = corr;
        }
        __syncthreads();

#pragma unroll
        for (int i = 0; i < 4; i++) {
            float c = sC[j0 + i];
            unsigned long long cc = f2_pack(c, c);
#pragma unroll
            for (int j = 0; j < 5; j++) acc[i][j] = f2_mul(acc[i][j], cc);
        }
#pragma unroll 2
        for (int kk = 0; kk < 64; kk++) {
            float4 pv = *(const float4*)&sSt[kk * QPAD + j0];
            unsigned long long vv[5];
#pragma unroll
            for (int j = 0; j < 5; j++)
                vv[j] = *(const unsigned long long*)&sV[kk * VPAD + cV + 2 * j];
            float pm[4] = {pv.x, pv.y, pv.z, pv.w};
#pragma unroll
            for (int i = 0; i < 4; i++) {
                unsigned long long pp = f2_pack(pm[i], pm[i]);
#pragma unroll
                for (int j = 0; j < 5; j++) acc[i][j] = f2_fma(pp, vv[j], acc[i][j]);
            }
        }
    }

#pragma unroll
    for (int i = 0; i < 4; i++) {
        float inv = 1.f / sL[j0 + i];
        size_t o = ((size_t)b * SEQ + qt * 64 + j0 + i) * DIM + h * HDIM + cV;
#pragma unroll
        for (int j = 0; j < 5; j++) {
            float lo, hi;
            f2_unpack(acc[i][j], lo, hi);
            *(float2*)(g_attn + o + 2 * j) = make_float2(lo * inv, hi * inv);
        }
    }
}

// ---------------- launch ----------------
extern "C" void kernel_launch(void* const* d_in, const int* in_sizes, int n_in,
                              void* d_out, int out_size) {
    (void)in_sizes; (void)n_in; (void)out_size;
    const float* x  = (const float*)d_in[0];
    const float* wq = (const float*)d_in[1];
    const float* wk = (const float*)d_in[2];
    const float* wv = (const float*)d_in[3];
    const float* wo = (const float*)d_in[4];
    const float* bo = (const float*)d_in[5];
    const float* qd = (const float*)d_in[6];
    const float* qu = (const float*)d_in[7];
    const float* kd = (const float*)d_in[8];
    const float* ku = (const float*)d_in[9];
    const float* vd = (const float*)d_in[10];
    const float* vu = (const float*)d_in[11];
    const float* od = (const float*)d_in[12];
    const float* ou = (const float*)d_in[13];
    float* out = (float*)d_out;

    fold_weights<<<dim3((DIM * DIM + 255) / 256, 4), 256>>>(
        wq, wk, wv, wo, qd, qu, kd, ku, vd, vu, od, ou);

    cudaFuncSetAttribute(qkv_gemm_w, cudaFuncAttributeMaxDynamicSharedMemorySize,
                         GEMM_SMEM_BYTES);
    qkv_gemm_w<<<dim3(DIM / 128, BS / 128, 3), 256, GEMM_SMEM_BYTES>>>(x);

    cudaFuncSetAttribute(flash_attn, cudaFuncAttributeMaxDynamicSharedMemorySize,
                         FLASH_SMEM_BYTES);
    flash_attn<<<dim3(SEQ / 64, HEADS, BATCH), 128, FLASH_SMEM_BYTES>>>();

    cudaFuncSetAttribute(out_gemm_w, cudaFuncAttributeMaxDynamicSharedMemorySize,
                         GEMM_SMEM_BYTES);
    out_gemm_w<<<dim3(DIM / 128, BS / 128), 256, GEMM_SMEM_BYTES>>>(bo, out);
}